// round 13
// baseline (speedup 1.0000x reference)
#include <cuda_runtime.h>
#include <cuda_bf16.h>
#include <cstdint>

#define Bn 8192
#define Dd 256
#define MT 64                  // anchors per m-tile
#define NTILE 32               // candidates per col-tile
#define TPM 130                // col-tiles per m-tile (4160 cols = 4096 + MT)
#define MTILES (Bn / MT)       // 128
#define TT (MTILES * TPM)      // 16640 global tiles
#define MGRID 444              // 148 SMs x occ 3

// smem layout (bytes): sqlb 2x32 float2 | A 64x512 | B 2 x 32x512
#define SM_SQLB 0
#define SM_A 1024
#define SM_B (SM_A + 32768)
#define SM_TOTAL (SM_B + 2 * 16384)   // 66560

typedef unsigned long long u64;
#define FINF __int_as_float(0x7F800000)

// ---- scratch (no allocation allowed) ----
__device__ float2 g_sqlab[Bn];
__device__ u64 g_pos[Bn];
__device__ u64 g_neg[Bn];
__device__ float g_loss[Bn];
__device__ int g_valid[Bn];
__device__ __nv_bfloat16 g_Xh[(size_t)Bn * Dd];   // 4MB bf16 copy

// ---------------- helpers ----------------
__device__ __forceinline__ uint32_t smem_u32(const void* p) {
    uint32_t a;
    asm("{ .reg .u64 t; cvta.to.shared.u64 t, %1; cvt.u32.u64 %0, t; }" : "=r"(a) : "l"(p));
    return a;
}
__device__ __forceinline__ void ldm_x4(uint32_t& r0, uint32_t& r1, uint32_t& r2, uint32_t& r3,
                                       uint32_t addr) {
    asm volatile("ldmatrix.sync.aligned.m8n8.x4.shared.b16 {%0,%1,%2,%3}, [%4];"
                 : "=r"(r0), "=r"(r1), "=r"(r2), "=r"(r3) : "r"(addr));
}
__device__ __forceinline__ void mma16816(float* c, const uint32_t* a, const uint32_t* b) {
    asm volatile(
        "mma.sync.aligned.m16n8k16.row.col.f32.bf16.bf16.f32 "
        "{%0,%1,%2,%3}, {%4,%5,%6,%7}, {%8,%9}, {%0,%1,%2,%3};"
        : "+f"(c[0]), "+f"(c[1]), "+f"(c[2]), "+f"(c[3])
        : "r"(a[0]), "r"(a[1]), "r"(a[2]), "r"(a[3]), "r"(b[0]), "r"(b[1]));
}
__device__ __forceinline__ void cp16(uint32_t dst, const void* src) {
    asm volatile("cp.async.cg.shared.global [%0], [%1], 16;" :: "r"(dst), "l"(src) : "memory");
}
__device__ __forceinline__ void cp8(uint32_t dst, const void* src) {
    asm volatile("cp.async.ca.shared.global [%0], [%1], 8;" :: "r"(dst), "l"(src) : "memory");
}
__device__ __forceinline__ void cp_commit() { asm volatile("cp.async.commit_group;" ::: "memory"); }
__device__ __forceinline__ void cp_wait0() { asm volatile("cp.async.wait_group 0;" ::: "memory"); }

// XOR swizzle: 512B logical rows, 16B chunks c in [0,32); permute low 3 bits by row
__device__ __forceinline__ uint32_t swz(int r, int c) {
    return (uint32_t)(r * 512 + ((((c & 24) | ((c ^ r) & 7))) << 4));
}

// ---------------- prep: warp per row; label-layout probe folded in ----------------
__global__ void prep_kernel(const float* __restrict__ X, const int* __restrict__ lab32) {
    int tid = threadIdx.x;
    int row = blockIdx.x * 8 + (tid >> 5);
    int lane = tid & 31;

    // int64 labels (values 0..7) => every odd 32-bit word is 0.
    int probe = (tid < 128) ? lab32[2 * tid + 1] : 0;
    bool l64 = (__syncthreads_or(probe != 0) == 0);

    const float4* x4 = (const float4*)(X + (size_t)row * Dd);
    float4 v0 = x4[2 * lane];
    float4 v1 = x4[2 * lane + 1];
    __nv_bfloat162 b0 = __nv_bfloat162(__float2bfloat16(v0.x), __float2bfloat16(v0.y));
    __nv_bfloat162 b1 = __nv_bfloat162(__float2bfloat16(v0.z), __float2bfloat16(v0.w));
    __nv_bfloat162 b2 = __nv_bfloat162(__float2bfloat16(v1.x), __float2bfloat16(v1.y));
    __nv_bfloat162 b3 = __nv_bfloat162(__float2bfloat16(v1.z), __float2bfloat16(v1.w));
    uint4 pk;
    pk.x = *(uint32_t*)&b0; pk.y = *(uint32_t*)&b1;
    pk.z = *(uint32_t*)&b2; pk.w = *(uint32_t*)&b3;
    *(uint4*)(g_Xh + (size_t)row * Dd + 8 * lane) = pk;

    float s = v0.x * v0.x + v0.y * v0.y + v0.z * v0.z + v0.w * v0.w
            + v1.x * v1.x + v1.y * v1.y + v1.z * v1.z + v1.w * v1.w;
#pragma unroll
    for (int o = 16; o > 0; o >>= 1) s += __shfl_xor_sync(0xffffffffu, s, o);
    if (lane == 0) {
        float2 sl;
        sl.x = s;
        sl.y = __int_as_float(l64 ? lab32[2 * row] : lab32[row]);
        g_sqlab[row] = sl;
        g_pos[row] = 0ull;
        g_neg[row] = ~0ull;
    }
}

// ---------------- HMMA fused GEMM + symmetric hard mining (occ 3, MT=64) ----------------
__global__ void __launch_bounds__(256, 3) mine_tc(void) {
    extern __shared__ char sm[];
    uint32_t smb = smem_u32(sm);
    int tid = threadIdx.x;
    int wid = tid >> 5;
    int lane = tid & 31;
    int bid = blockIdx.x;

    uint32_t g0 = ((uint32_t)bid * TT) / MGRID;
    uint32_t g1 = ((uint32_t)(bid + 1) * TT) / MGRID;

    int mw = wid & 3;          // m-warp: rows mw*16 + [0,16)
    int nw = wid >> 2;         // n-warp: cols nw*16 + [0,16)
    int frow = lane & 15;      // fragment row/col index for ldmatrix
    int bkh = lane >> 4;       // k-half
    bool colrep = (lane & 12) == 0;   // lanes 0-3 and 16-19
    int arow = mw * 16 + frow;
    int brow = nw * 16 + frow;

    uint32_t g = g0;
    while (g < g1) {
        int m = (int)(g / TPM);
        uint32_t gme = min(g1, (uint32_t)(m + 1) * TPM);
        int row0 = m * MT;

        // ---- segment prologue: A(m) + first B tile + sqlb ----
        for (int i = tid; i < MT * 32; i += 256) {
            int r = i >> 5, c = i & 31;
            cp16(smb + SM_A + swz(r, c), g_Xh + (size_t)(row0 + r) * Dd + 8 * c);
        }
        {
            int w = (int)(g - (uint32_t)m * TPM);
            int cb = (row0 + w * 32) & (Bn - 1);
            for (int i = tid; i < NTILE * 32; i += 256) {
                int r = i >> 5, c = i & 31;
                cp16(smb + SM_B + swz(r, c), g_Xh + (size_t)(cb + r) * Dd + 8 * c);
            }
            if (tid < NTILE) cp8(smb + SM_SQLB + tid * 8, g_sqlab + cb + tid);
        }
        cp_commit();

        // row metadata for this m (2 rows per thread)
        float mysq[2];
        int mylab[2], myrowg[2];
#pragma unroll
        for (int h = 0; h < 2; h++) {
            int rg = row0 + mw * 16 + h * 8 + (lane >> 2);
            float2 sl = g_sqlab[rg];
            mysq[h] = sl.x;
            mylab[h] = __float_as_int(sl.y);
            myrowg[h] = rg;
        }
        float rbP[2] = {-1.f, -1.f};
        float rbN[2] = {FINF, FINF};
        int rbPi[2] = {0, 0};
        int rbNi[2] = {0, 0};

        cp_wait0();
        __syncthreads();

        // ---- hoist half the A fragments (ks 0..7) into registers ----
        uint32_t a8[8][4];
#pragma unroll
        for (int ks = 0; ks < 8; ks++)
            ldm_x4(a8[ks][0], a8[ks][1], a8[ks][2], a8[ks][3],
                   smb + SM_A + swz(arow, 2 * ks + bkh));

#pragma unroll 1
        for (uint32_t t = g; t < gme; t++) {
            int buf = (int)((t - g) & 1u);
            int w = (int)(t - (uint32_t)m * TPM);
            int cb = (row0 + w * 32) & (Bn - 1);

            // prefetch next tile within this segment
            if (t + 1 < gme) {
                int cb2 = (row0 + (w + 1) * 32) & (Bn - 1);
                uint32_t bdst = smb + SM_B + (uint32_t)((buf ^ 1) * 16384);
                for (int i = tid; i < NTILE * 32; i += 256) {
                    int r = i >> 5, c = i & 31;
                    cp16(bdst + swz(r, c), g_Xh + (size_t)(cb2 + r) * Dd + 8 * c);
                }
                if (tid < NTILE)
                    cp8(smb + SM_SQLB + (buf ^ 1) * 256 + tid * 8, g_sqlab + cb2 + tid);
                cp_commit();
            }

            // ---- GEMM 64x32x256: per warp 16x16, 2 HMMA per kstep ----
            float acc[2][4];
#pragma unroll
            for (int nf = 0; nf < 2; nf++)
#pragma unroll
                for (int j = 0; j < 4; j++) acc[nf][j] = 0.f;

            uint32_t bbuf = smb + SM_B + (uint32_t)(buf * 16384);
#pragma unroll
            for (int ks = 0; ks < 16; ks++) {
                int chunk = 2 * ks + bkh;
                uint32_t av[4];
                if (ks < 8) {
                    av[0] = a8[ks][0]; av[1] = a8[ks][1];
                    av[2] = a8[ks][2]; av[3] = a8[ks][3];
                } else {
                    ldm_x4(av[0], av[1], av[2], av[3],
                           smb + SM_A + swz(arow, chunk));
                }
                uint32_t b[2][2];
                {
                    uint32_t r0, r1, r2, r3;
                    ldm_x4(r0, r1, r2, r3, bbuf + swz(brow, chunk));
                    b[0][0] = r0; b[1][0] = r1; b[0][1] = r2; b[1][1] = r3;
                }
                mma16816(acc[0], av, b[0]);
                mma16816(acc[1], av, b[1]);
            }

            // ---- two-sided mining epilogue (4 slots/warp) ----
            const float2* sq2 = (const float2*)(sm + SM_SQLB + buf * 256);
#pragma unroll
            for (int nf = 0; nf < 2; nf++)
#pragma unroll
                for (int e = 0; e < 2; e++) {
                    int cl = nw * 16 + nf * 8 + 2 * (lane & 3) + e;
                    float2 sl = sq2[cl];
                    int colg = cb + cl;
                    int clab = __float_as_int(sl.y);
                    u64 cp = 0ull, cn = ~0ull;
#pragma unroll
                    for (int h = 0; h < 2; h++) {
                        float d2 = fmaxf(fmaf(-2.f, acc[nf][h * 2 + e], mysq[h] + sl.x), 0.f);
                        uint32_t db = __float_as_uint(d2);
                        if (clab == mylab[h]) {
                            if (colg != myrowg[h]) {
                                if (d2 > rbP[h]) { rbP[h] = d2; rbPi[h] = colg; }
                                u64 ck = ((u64)db << 32) | (uint32_t)(~(uint32_t)myrowg[h]);
                                if (ck > cp) cp = ck;
                            }
                        } else {
                            if (d2 < rbN[h]) { rbN[h] = d2; rbNi[h] = colg; }
                            u64 ck = ((u64)db << 32) | (uint32_t)myrowg[h];
                            if (ck < cn) cn = ck;
                        }
                    }
                    // 2-step coset reduce (strides 4,8)
#pragma unroll
                    for (int s = 4; s <= 8; s <<= 1) {
                        u64 p = __shfl_xor_sync(0xffffffffu, cp, s);
                        if (p > cp) cp = p;
                        u64 q = __shfl_xor_sync(0xffffffffu, cn, s);
                        if (q < cn) cn = q;
                    }
                    if (colrep) {
                        atomicMax(&g_pos[colg], cp);
                        atomicMin(&g_neg[colg], cn);
                    }
                }

            if (t + 1 < gme) cp_wait0();
            __syncthreads();
        }

        // ---- row-side merge for this m: quad shfl (tie -> lowest idx), then atomics ----
#pragma unroll
        for (int h = 0; h < 2; h++) {
#pragma unroll
            for (int o = 1; o < 4; o <<= 1) {
                float od = __shfl_xor_sync(0xffffffffu, rbP[h], o);
                int oi = __shfl_xor_sync(0xffffffffu, rbPi[h], o);
                if (od > rbP[h] || (od == rbP[h] && oi < rbPi[h])) { rbP[h] = od; rbPi[h] = oi; }
                float ed = __shfl_xor_sync(0xffffffffu, rbN[h], o);
                int ei = __shfl_xor_sync(0xffffffffu, rbNi[h], o);
                if (ed < rbN[h] || (ed == rbN[h] && ei < rbNi[h])) { rbN[h] = ed; rbNi[h] = ei; }
            }
            if ((lane & 3) == 0) {
                if (rbP[h] >= 0.f)
                    atomicMax(&g_pos[myrowg[h]],
                              ((u64)__float_as_uint(rbP[h]) << 32) | (uint32_t)(~(uint32_t)rbPi[h]));
                if (rbN[h] < FINF)
                    atomicMin(&g_neg[myrowg[h]],
                              ((u64)__float_as_uint(rbN[h]) << 32) | (uint32_t)rbNi[h]);
            }
        }

        g = gme;
    }
}

// ---------------- exact per-anchor recompute: warp per anchor ----------------
__global__ void loss_kernel(const float* __restrict__ X) {
    int a = blockIdx.x * 8 + (threadIdx.x >> 5);
    int lane = threadIdx.x & 31;
    u64 p = g_pos[a];
    u64 q = g_neg[a];
    bool valid = (p != 0ull) && (q != ~0ull);
    float lp = 0.f, ln = 0.f;
    if (valid) {
        int pi = (int)(~(uint32_t)(p & 0xFFFFFFFFull));
        int ni = (int)(uint32_t)(q & 0xFFFFFFFFull);
        const float4* va = (const float4*)(X + (size_t)a * Dd);
        const float4* vp = (const float4*)(X + (size_t)pi * Dd);
        const float4* vn = (const float4*)(X + (size_t)ni * Dd);
#pragma unroll
        for (int u = 0; u < 2; u++) {
            float4 x = va[2 * lane + u];
            float4 y = vp[2 * lane + u];
            float4 z = vn[2 * lane + u];
            float d;
            d = x.x - y.x + 1e-6f; lp += d * d;
            d = x.y - y.y + 1e-6f; lp += d * d;
            d = x.z - y.z + 1e-6f; lp += d * d;
            d = x.w - y.w + 1e-6f; lp += d * d;
            d = x.x - z.x + 1e-6f; ln += d * d;
            d = x.y - z.y + 1e-6f; ln += d * d;
            d = x.z - z.z + 1e-6f; ln += d * d;
            d = x.w - z.w + 1e-6f; ln += d * d;
        }
    }
#pragma unroll
    for (int o = 16; o > 0; o >>= 1) {
        lp += __shfl_xor_sync(0xffffffffu, lp, o);
        ln += __shfl_xor_sync(0xffffffffu, ln, o);
    }
    if (lane == 0) {
        float v = sqrtf(lp) - sqrtf(ln) + 0.3f;
        g_loss[a] = valid ? (v > 0.f ? v : 0.f) : 0.f;
        g_valid[a] = valid ? 1 : 0;
    }
}

// ---------------- deterministic final reduction (shfl tree, 1 barrier) ----------------
__global__ void final_kernel(float* __restrict__ out) {
    int t = threadIdx.x;   // 1024
    int lane = t & 31, w = t >> 5;
    float s = 0.f;
    float c = 0.f;
#pragma unroll
    for (int j = 0; j < Bn / 1024; j++) {
        s += g_loss[t + j * 1024];
        c += (float)g_valid[t + j * 1024];
    }
#pragma unroll
    for (int o = 16; o > 0; o >>= 1) {
        s += __shfl_xor_sync(0xffffffffu, s, o);
        c += __shfl_xor_sync(0xffffffffu, c, o);
    }
    __shared__ float ws[32], wc[32];
    if (lane == 0) { ws[w] = s; wc[w] = c; }
    __syncthreads();
    if (w == 0) {
        s = ws[lane];
        c = wc[lane];
#pragma unroll
        for (int o = 16; o > 0; o >>= 1) {
            s += __shfl_xor_sync(0xffffffffu, s, o);
            c += __shfl_xor_sync(0xffffffffu, c, o);
        }
        if (lane == 0) out[0] = s / fmaxf(c, 1.f);
    }
}

extern "C" void kernel_launch(void* const* d_in, const int* in_sizes, int n_in,
                              void* d_out, int out_size) {
    const float* X = (const float*)d_in[0];
    const int* lab32 = (const int*)d_in[1];
    float* out = (float*)d_out;

    cudaFuncSetAttribute(mine_tc, cudaFuncAttributeMaxDynamicSharedMemorySize, SM_TOTAL);

    prep_kernel<<<Bn / 8, 256>>>(X, lab32);
    mine_tc<<<MGRID, 256, SM_TOTAL>>>();
    loss_kernel<<<Bn / 8, 256>>>(X);
    final_kernel<<<1, 1024>>>(out);
}

// round 14
// speedup vs baseline: 1.1945x; 1.1945x over previous
#include <cuda_runtime.h>
#include <cuda_bf16.h>
#include <cstdint>

#define Bn 8192
#define Dd 256
#define MT 128                 // anchors per m-tile
#define NTILE 32               // candidates per col-tile
#define TPM 132                // col-tiles per m-tile (4224 cols = forward half-circle)
#define TT (64 * TPM)          // 8448 global tiles
#define MGRID 296              // 148 SMs x occ 2, near-equal static ranges

// smem layout (bytes): sqlb 2x32 float2 | A 128x512 | B 2 x 32x512
#define SM_SQLB 0
#define SM_A 1024
#define SM_B (SM_A + 65536)
#define SM_TOTAL (SM_B + 2 * 16384)   // 99328

typedef unsigned long long u64;
#define FINF __int_as_float(0x7F800000)
#define FPSCALE 16777216.0f    // 2^24 fixed-point for deterministic loss sum

// ---- scratch (no allocation allowed) ----
__device__ float2 g_sqlab[Bn];
__device__ u64 g_pos[Bn];
__device__ u64 g_neg[Bn];
__device__ __nv_bfloat16 g_Xh[(size_t)Bn * Dd];   // 4MB bf16 copy
__device__ u64 g_sumloss;
__device__ int g_sumvalid;
__device__ int g_done;

// ---------------- helpers ----------------
__device__ __forceinline__ uint32_t smem_u32(const void* p) {
    uint32_t a;
    asm("{ .reg .u64 t; cvta.to.shared.u64 t, %1; cvt.u32.u64 %0, t; }" : "=r"(a) : "l"(p));
    return a;
}
__device__ __forceinline__ void ldm_x4(uint32_t& r0, uint32_t& r1, uint32_t& r2, uint32_t& r3,
                                       uint32_t addr) {
    asm volatile("ldmatrix.sync.aligned.m8n8.x4.shared.b16 {%0,%1,%2,%3}, [%4];"
                 : "=r"(r0), "=r"(r1), "=r"(r2), "=r"(r3) : "r"(addr));
}
__device__ __forceinline__ void mma16816(float* c, const uint32_t* a, const uint32_t* b) {
    asm volatile(
        "mma.sync.aligned.m16n8k16.row.col.f32.bf16.bf16.f32 "
        "{%0,%1,%2,%3}, {%4,%5,%6,%7}, {%8,%9}, {%0,%1,%2,%3};"
        : "+f"(c[0]), "+f"(c[1]), "+f"(c[2]), "+f"(c[3])
        : "r"(a[0]), "r"(a[1]), "r"(a[2]), "r"(a[3]), "r"(b[0]), "r"(b[1]));
}
__device__ __forceinline__ void cp16(uint32_t dst, const void* src) {
    asm volatile("cp.async.cg.shared.global [%0], [%1], 16;" :: "r"(dst), "l"(src) : "memory");
}
__device__ __forceinline__ void cp8(uint32_t dst, const void* src) {
    asm volatile("cp.async.ca.shared.global [%0], [%1], 8;" :: "r"(dst), "l"(src) : "memory");
}
__device__ __forceinline__ void cp_commit() { asm volatile("cp.async.commit_group;" ::: "memory"); }
__device__ __forceinline__ void cp_wait0() { asm volatile("cp.async.wait_group 0;" ::: "memory"); }

// XOR swizzle: 512B logical rows, 16B chunks c in [0,32); permute low 3 bits by row
__device__ __forceinline__ uint32_t swz(int r, int c) {
    return (uint32_t)(r * 512 + ((((c & 24) | ((c ^ r) & 7))) << 4));
}

// ---------------- prep: warp per row; label probe + accumulator reset folded in ----------------
__global__ void prep_kernel(const float* __restrict__ X, const int* __restrict__ lab32) {
    int tid = threadIdx.x;
    int row = blockIdx.x * 8 + (tid >> 5);
    int lane = tid & 31;

    if (blockIdx.x == 0 && tid == 0) {
        g_sumloss = 0ull;
        g_sumvalid = 0;
        g_done = 0;
    }

    // int64 labels (values 0..7) => every odd 32-bit word is 0.
    int probe = (tid < 128) ? lab32[2 * tid + 1] : 0;
    bool l64 = (__syncthreads_or(probe != 0) == 0);

    const float4* x4 = (const float4*)(X + (size_t)row * Dd);
    float4 v0 = x4[2 * lane];
    float4 v1 = x4[2 * lane + 1];
    __nv_bfloat162 b0 = __nv_bfloat162(__float2bfloat16(v0.x), __float2bfloat16(v0.y));
    __nv_bfloat162 b1 = __nv_bfloat162(__float2bfloat16(v0.z), __float2bfloat16(v0.w));
    __nv_bfloat162 b2 = __nv_bfloat162(__float2bfloat16(v1.x), __float2bfloat16(v1.y));
    __nv_bfloat162 b3 = __nv_bfloat162(__float2bfloat16(v1.z), __float2bfloat16(v1.w));
    uint4 pk;
    pk.x = *(uint32_t*)&b0; pk.y = *(uint32_t*)&b1;
    pk.z = *(uint32_t*)&b2; pk.w = *(uint32_t*)&b3;
    *(uint4*)(g_Xh + (size_t)row * Dd + 8 * lane) = pk;

    float s = v0.x * v0.x + v0.y * v0.y + v0.z * v0.z + v0.w * v0.w
            + v1.x * v1.x + v1.y * v1.y + v1.z * v1.z + v1.w * v1.w;
#pragma unroll
    for (int o = 16; o > 0; o >>= 1) s += __shfl_xor_sync(0xffffffffu, s, o);
    if (lane == 0) {
        float2 sl;
        sl.x = s;
        sl.y = __int_as_float(l64 ? lab32[2 * row] : lab32[row]);
        g_sqlab[row] = sl;
        g_pos[row] = 0ull;
        g_neg[row] = ~0ull;
    }
}

// ---------------- HMMA fused GEMM + symmetric hard mining (balanced linear grid) ----------------
__global__ void __launch_bounds__(256, 2) mine_tc(void) {
    extern __shared__ char sm[];
    uint32_t smb = smem_u32(sm);
    int tid = threadIdx.x;
    int wid = tid >> 5;        // warp owns rows wid*16 .. wid*16+15
    int lane = tid & 31;
    int bid = blockIdx.x;

    uint32_t g0 = ((uint32_t)bid * TT) / MGRID;
    uint32_t g1 = ((uint32_t)(bid + 1) * TT) / MGRID;

    int brow01 = lane & 15;
    int bkh = lane >> 4;
    bool colrep = (lane & 12) == 0;   // lanes 0-3 and 16-19: coset representatives
    int arow = wid * 16 + (lane & 15);

    uint32_t g = g0;
    while (g < g1) {
        int m = (int)(g / TPM);
        uint32_t gme = min(g1, (uint32_t)(m + 1) * TPM);
        int row0 = m * MT;

        // ---- segment prologue: A(m) + first B tile + sqlb ----
        for (int i = tid; i < MT * 32; i += 256) {
            int r = i >> 5, c = i & 31;
            cp16(smb + SM_A + swz(r, c), g_Xh + (size_t)(row0 + r) * Dd + 8 * c);
        }
        {
            int w = (int)(g - (uint32_t)m * TPM);
            int cb = (row0 + w * 32) & (Bn - 1);
            for (int i = tid; i < NTILE * 32; i += 256) {
                int r = i >> 5, c = i & 31;
                cp16(smb + SM_B + swz(r, c), g_Xh + (size_t)(cb + r) * Dd + 8 * c);
            }
            if (tid < NTILE) cp8(smb + SM_SQLB + tid * 8, g_sqlab + cb + tid);
        }
        cp_commit();

        // row metadata for this m (2 rows per thread)
        float mysq[2];
        int mylab[2], myrowg[2];
#pragma unroll
        for (int h = 0; h < 2; h++) {
            int rg = row0 + wid * 16 + h * 8 + (lane >> 2);
            float2 sl = g_sqlab[rg];
            mysq[h] = sl.x;
            mylab[h] = __float_as_int(sl.y);
            myrowg[h] = rg;
        }
        float rbP[2] = {-1.f, -1.f};
        float rbN[2] = {FINF, FINF};
        int rbPi[2] = {0, 0};
        int rbNi[2] = {0, 0};

        cp_wait0();
        __syncthreads();

        // ---- hoist A fragments into registers (segment-invariant) ----
        uint32_t a[16][4];
#pragma unroll
        for (int ks = 0; ks < 16; ks++)
            ldm_x4(a[ks][0], a[ks][1], a[ks][2], a[ks][3],
                   smb + SM_A + swz(arow, 2 * ks + bkh));

#pragma unroll 1
        for (uint32_t t = g; t < gme; t++) {
            int buf = (int)((t - g) & 1u);
            int w = (int)(t - (uint32_t)m * TPM);
            int cb = (row0 + w * 32) & (Bn - 1);

            // prefetch next tile within this segment
            if (t + 1 < gme) {
                int cb2 = (row0 + (w + 1) * 32) & (Bn - 1);
                uint32_t bdst = smb + SM_B + (uint32_t)((buf ^ 1) * 16384);
                for (int i = tid; i < NTILE * 32; i += 256) {
                    int r = i >> 5, c = i & 31;
                    cp16(bdst + swz(r, c), g_Xh + (size_t)(cb2 + r) * Dd + 8 * c);
                }
                if (tid < NTILE)
                    cp8(smb + SM_SQLB + (buf ^ 1) * 256 + tid * 8, g_sqlab + cb2 + tid);
                cp_commit();
            }

            // ---- GEMM 128x32x256: per warp 16x32, 4 HMMA per kstep ----
            float acc[4][4];
#pragma unroll
            for (int nf = 0; nf < 4; nf++)
#pragma unroll
                for (int j = 0; j < 4; j++) acc[nf][j] = 0.f;

            uint32_t bbuf = smb + SM_B + (uint32_t)(buf * 16384);
#pragma unroll
            for (int ks = 0; ks < 16; ks++) {
                int chunk = 2 * ks + bkh;
                uint32_t b[4][2];
                {
                    uint32_t r0, r1, r2, r3;
                    ldm_x4(r0, r1, r2, r3, bbuf + swz(brow01, chunk));
                    b[0][0] = r0; b[1][0] = r1; b[0][1] = r2; b[1][1] = r3;
                    ldm_x4(r0, r1, r2, r3, bbuf + swz(16 + brow01, chunk));
                    b[2][0] = r0; b[3][0] = r1; b[2][1] = r2; b[3][1] = r3;
                }
#pragma unroll
                for (int nf = 0; nf < 4; nf++)
                    mma16816(acc[nf], a[ks], b[nf]);
            }

            // ---- two-sided mining epilogue (vectorized sqlb load per nf) ----
            const float4* sq4 = (const float4*)(sm + SM_SQLB + buf * 256);
#pragma unroll
            for (int nf = 0; nf < 4; nf++) {
                float4 sv = sq4[nf * 4 + (lane & 3)];   // cols cl0, cl0+1
#pragma unroll
                for (int e = 0; e < 2; e++) {
                    int cl = nf * 8 + 2 * (lane & 3) + e;
                    float slsq = e ? sv.z : sv.x;
                    int clab = __float_as_int(e ? sv.w : sv.y);
                    int colg = cb + cl;
                    u64 cp = 0ull, cn = ~0ull;
#pragma unroll
                    for (int h = 0; h < 2; h++) {
                        float d2 = fmaxf(fmaf(-2.f, acc[nf][h * 2 + e], mysq[h] + slsq), 0.f);
                        uint32_t db = __float_as_uint(d2);
                        if (clab == mylab[h]) {
                            if (colg != myrowg[h]) {
                                if (d2 > rbP[h]) { rbP[h] = d2; rbPi[h] = colg; }
                                u64 ck = ((u64)db << 32) | (uint32_t)(~(uint32_t)myrowg[h]);
                                if (ck > cp) cp = ck;
                            }
                        } else {
                            if (d2 < rbN[h]) { rbN[h] = d2; rbNi[h] = colg; }
                            u64 ck = ((u64)db << 32) | (uint32_t)myrowg[h];
                            if (ck < cn) cn = ck;
                        }
                    }
                    // 2-step coset reduce (strides 4,8)
#pragma unroll
                    for (int s = 4; s <= 8; s <<= 1) {
                        u64 p = __shfl_xor_sync(0xffffffffu, cp, s);
                        if (p > cp) cp = p;
                        u64 q = __shfl_xor_sync(0xffffffffu, cn, s);
                        if (q < cn) cn = q;
                    }
                    if (colrep) {
                        atomicMax(&g_pos[colg], cp);
                        atomicMin(&g_neg[colg], cn);
                    }
                }
            }

            if (t + 1 < gme) cp_wait0();
            __syncthreads();
        }

        // ---- row-side merge for this m: quad shfl (tie -> lowest idx), then atomics ----
#pragma unroll
        for (int h = 0; h < 2; h++) {
#pragma unroll
            for (int o = 1; o < 4; o <<= 1) {
                float od = __shfl_xor_sync(0xffffffffu, rbP[h], o);
                int oi = __shfl_xor_sync(0xffffffffu, rbPi[h], o);
                if (od > rbP[h] || (od == rbP[h] && oi < rbPi[h])) { rbP[h] = od; rbPi[h] = oi; }
                float ed = __shfl_xor_sync(0xffffffffu, rbN[h], o);
                int ei = __shfl_xor_sync(0xffffffffu, rbNi[h], o);
                if (ed < rbN[h] || (ed == rbN[h] && ei < rbNi[h])) { rbN[h] = ed; rbNi[h] = ei; }
            }
            if ((lane & 3) == 0) {
                if (rbP[h] >= 0.f)
                    atomicMax(&g_pos[myrowg[h]],
                              ((u64)__float_as_uint(rbP[h]) << 32) | (uint32_t)(~(uint32_t)rbPi[h]));
                if (rbN[h] < FINF)
                    atomicMin(&g_neg[myrowg[h]],
                              ((u64)__float_as_uint(rbN[h]) << 32) | (uint32_t)rbNi[h]);
            }
        }

        g = gme;
    }
}

// ---------------- exact recompute + fused deterministic final reduction ----------------
__global__ void loss_kernel(const float* __restrict__ X, float* __restrict__ out) {
    int tid = threadIdx.x;
    int a = blockIdx.x * 8 + (tid >> 5);
    int lane = tid & 31;
    u64 p = g_pos[a];
    u64 q = g_neg[a];
    bool valid = (p != 0ull) && (q != ~0ull);
    float lp = 0.f, ln = 0.f;
    if (valid) {
        int pi = (int)(~(uint32_t)(p & 0xFFFFFFFFull));
        int ni = (int)(uint32_t)(q & 0xFFFFFFFFull);
        const float4* va = (const float4*)(X + (size_t)a * Dd);
        const float4* vp = (const float4*)(X + (size_t)pi * Dd);
        const float4* vn = (const float4*)(X + (size_t)ni * Dd);
#pragma unroll
        for (int u = 0; u < 2; u++) {
            float4 x = va[2 * lane + u];
            float4 y = vp[2 * lane + u];
            float4 z = vn[2 * lane + u];
            float d;
            d = x.x - y.x + 1e-6f; lp += d * d;
            d = x.y - y.y + 1e-6f; lp += d * d;
            d = x.z - y.z + 1e-6f; lp += d * d;
            d = x.w - y.w + 1e-6f; lp += d * d;
            d = x.x - z.x + 1e-6f; ln += d * d;
            d = x.y - z.y + 1e-6f; ln += d * d;
            d = x.z - z.z + 1e-6f; ln += d * d;
            d = x.w - z.w + 1e-6f; ln += d * d;
        }
    }
#pragma unroll
    for (int o = 16; o > 0; o >>= 1) {
        lp += __shfl_xor_sync(0xffffffffu, lp, o);
        ln += __shfl_xor_sync(0xffffffffu, ln, o);
    }
    __shared__ float wl[8];
    __shared__ int wv[8];
    if (lane == 0) {
        float v = sqrtf(lp) - sqrtf(ln) + 0.3f;
        wl[tid >> 5] = valid ? (v > 0.f ? v : 0.f) : 0.f;
        wv[tid >> 5] = valid ? 1 : 0;
    }
    __syncthreads();
    if (tid == 0) {
        float s = 0.f;
        int c = 0;
#pragma unroll
        for (int j = 0; j < 8; j++) { s += wl[j]; c += wv[j]; }
        atomicAdd(&g_sumloss, (u64)llrintf(s * FPSCALE));
        atomicAdd(&g_sumvalid, c);
        __threadfence();
        int old = atomicAdd(&g_done, 1);
        if (old == gridDim.x - 1) {
            u64 tot = atomicAdd(&g_sumloss, 0ull);
            int cnt = atomicAdd(&g_sumvalid, 0);
            out[0] = (float)((double)tot / (double)FPSCALE / (double)(cnt > 0 ? cnt : 1));
        }
    }
}

extern "C" void kernel_launch(void* const* d_in, const int* in_sizes, int n_in,
                              void* d_out, int out_size) {
    const float* X = (const float*)d_in[0];
    const int* lab32 = (const int*)d_in[1];
    float* out = (float*)d_out;

    cudaFuncSetAttribute(mine_tc, cudaFuncAttributeMaxDynamicSharedMemorySize, SM_TOTAL);

    prep_kernel<<<Bn / 8, 256>>>(X, lab32);
    mine_tc<<<MGRID, 256, SM_TOTAL>>>();
    loss_kernel<<<Bn / 8, 256>>>(X, out);
}